// round 15
// baseline (speedup 1.0000x reference)
#include <cuda_runtime.h>
#include <cuda_bf16.h>
#include <math.h>

#define DIMC 512
#define EC   336
#define DST  16
#define HEADSC 6
#define HDC  56
#define BB   8
#define LL   4096
#define NN   32768        // B*L
#define KC   819          // int(L*0.2)
#define QKVW 1008         // 3*E
#define DTAP 128          // FIR truncation of the SSM impulse response

typedef unsigned long long ull;

// packed fp32x2 helpers (Blackwell FFMA2 — only reachable via PTX)
__device__ __forceinline__ ull pack2(float x) {
    ull r; asm("mov.b64 %0, {%1, %1};" : "=l"(r) : "f"(x)); return r;
}
__device__ __forceinline__ void ffma2(ull& d, ull a, ull b) {
    asm("fma.rn.f32x2 %0, %1, %2, %0;" : "+l"(d) : "l"(a), "l"(b));
}

// ---------------- scratch (device globals; no allocation) ----------------
__device__ __align__(128) float g_xp [(size_t)NN * EC];       // DyT(x) @ W_in + b_in
__device__ __align__(128) float g_nrm[NN];                    // max(||xp||, 1e-12)
__device__ __align__(128) float g_qkv[(size_t)NN * QKVW];     // qkv
__device__ __align__(128) float g_att[(size_t)NN * EC];       // attn out, e=d*6+h
__device__ __align__(128) float g_imp[NN];                    // sum-of-squares importance
__device__ __align__(128) int   g_idx[BB * KC];               // top-KC indices, rank order
__device__ __align__(128) float g_xct[(size_t)BB * EC * KC];  // conv output, (b,e,t)
__device__ __align__(128) float g_ys [(size_t)BB * KC * EC];  // FIR output (b,t,e)
__device__ __align__(128) float g_v  [DTAP * DST];            // A^d @ sigmoid(Bp)
__device__ __align__(128) float g_w  [EC * DTAP];             // FIR taps per channel

// ---------------- K3: row norms of xp ----------------
__global__ void norm_kernel() {
    int warp = (blockIdx.x * blockDim.x + threadIdx.x) >> 5;
    int lane = threadIdx.x & 31;
    if (warp >= NN) return;
    const float* row = g_xp + (size_t)warp * EC;
    float s = 0.f;
    for (int e = lane; e < EC; e += 32) { float v = row[e]; s = fmaf(v, v, s); }
    #pragma unroll
    for (int o = 16; o; o >>= 1) s += __shfl_xor_sync(0xffffffffu, s, o);
    if (lane == 0) g_nrm[warp] = fmaxf(sqrtf(s), 1e-12f);
}

// ---------------- fast fp32 GEMM: 128x128 tile, k-chunk 16, warp-tiled 8x8, FFMA2 ----------------
// C[M,Nc] = f(A)[M,K] @ B[K,Nc] + bias[n]
//   f = DyT (tanh(alpha*a)*dytw[k]+dytb[k]) when dytw != nullptr  (elementwise, bit-exact)
//   f = a / rowdiv[m]                       when rowdiv != nullptr
// Requires: M % 128 == 0, K % 16 == 0.
// Per-element accumulation: single register, strictly ascending k -> bit-identical.
__global__ void __launch_bounds__(256, 2)
gemm128_kernel(const float* __restrict__ A, const float* __restrict__ B,
               const float* __restrict__ bias,
               const float* __restrict__ rowdiv,
               const float* __restrict__ dytw,
               const float* __restrict__ dytb,
               const float* __restrict__ alphap,
               float* __restrict__ C,
               int M, int Nc, int K) {
    __shared__ float As[2][16][128];
    __shared__ float Bs[2][16][128];
    int tid = threadIdx.x;                 // 256 threads
    int bm = blockIdx.y * 128, bn = blockIdx.x * 128;

    int wid = tid >> 5, lane = tid & 31;
    int wm = wid & 3, wn = wid >> 2;       // 4 x 2 warps
    int lm = lane >> 3, ln = lane & 7;     // 4 x 8 lanes
    int row0 = wm * 32 + lm * 4;
    int col0 = wn * 64 + ln * 4;

    // A loader: two float4 per thread per chunk (rows 0..127, k-halves 0/4 + 8/12)
    int arow = tid >> 1;                   // 0..127
    int akc  = (tid & 1) * 4;              // 0 or 4
    const float* Aptr = A + (size_t)(bm + arow) * K + akc;
    float dv = rowdiv ? rowdiv[bm + arow] : 1.f;
    float alp = alphap ? alphap[0] : 0.f;

    // B loader: two float4 per thread per chunk (k-rows brow and brow+8)
    int brow = tid >> 5;                   // 0..7
    int bc4  = (tid & 31) * 4;             // 0..124
    int bcol = bn + bc4;

    ull acc2[8][4] = {};

    #define XFORM_A(av, koff)                                              \
        {                                                                  \
            if (dytw) {                                                    \
                float4 w4 = *(const float4*)&dytw[(koff) + akc];           \
                float4 b4 = *(const float4*)&dytb[(koff) + akc];           \
                av.x = tanhf(alp * av.x) * w4.x + b4.x;                    \
                av.y = tanhf(alp * av.y) * w4.y + b4.y;                    \
                av.z = tanhf(alp * av.z) * w4.z + b4.z;                    \
                av.w = tanhf(alp * av.w) * w4.w + b4.w;                    \
            } else if (rowdiv) {                                           \
                av.x /= dv; av.y /= dv; av.z /= dv; av.w /= dv;            \
            }                                                              \
        }

    #define LOAD_B(bv, krow)                                               \
        {                                                                  \
            const float* Brow_ = B + (size_t)(krow) * Nc;                  \
            if (bcol + 3 < Nc) bv = *(const float4*)&Brow_[bcol];          \
            else {                                                         \
                bv.x = (bcol + 0 < Nc) ? Brow_[bcol + 0] : 0.f;            \
                bv.y = (bcol + 1 < Nc) ? Brow_[bcol + 1] : 0.f;            \
                bv.z = (bcol + 2 < Nc) ? Brow_[bcol + 2] : 0.f;            \
                bv.w = (bcol + 3 < Nc) ? Brow_[bcol + 3] : 0.f;            \
            }                                                              \
        }

    // prologue: chunk 0 -> buffer 0
    {
        float4 av0 = *(const float4*)(Aptr);
        float4 av1 = *(const float4*)(Aptr + 8);
        XFORM_A(av0, 0); XFORM_A(av1, 8);
        As[0][akc + 0][arow] = av0.x;
        As[0][akc + 1][arow] = av0.y;
        As[0][akc + 2][arow] = av0.z;
        As[0][akc + 3][arow] = av0.w;
        As[0][akc + 8][arow] = av1.x;
        As[0][akc + 9][arow] = av1.y;
        As[0][akc +10][arow] = av1.z;
        As[0][akc +11][arow] = av1.w;
        float4 bv0, bv1;
        LOAD_B(bv0, brow);
        LOAD_B(bv1, brow + 8);
        *(float4*)&Bs[0][brow][bc4]     = bv0;
        *(float4*)&Bs[0][brow + 8][bc4] = bv1;
    }
    __syncthreads();

    int buf = 0;
    for (int k0 = 0; k0 < K; k0 += 16) {
        bool has_next = (k0 + 16) < K;
        float4 av0, av1, bv0, bv1;
        if (has_next) {
            av0 = *(const float4*)(Aptr + k0 + 16);
            av1 = *(const float4*)(Aptr + k0 + 24);
            XFORM_A(av0, k0 + 16); XFORM_A(av1, k0 + 24);
            LOAD_B(bv0, k0 + 16 + brow);
            LOAD_B(bv1, k0 + 24 + brow);
        }

        #pragma unroll
        for (int kk = 0; kk < 16; kk++) {
            float4 a0 = *(float4*)&As[buf][kk][row0];
            float4 a1 = *(float4*)&As[buf][kk][row0 + 16];
            ulonglong2 bq0 = *(ulonglong2*)&Bs[buf][kk][col0];
            ulonglong2 bq1 = *(ulonglong2*)&Bs[buf][kk][col0 + 32];
            ull bb[4] = {bq0.x, bq0.y, bq1.x, bq1.y};
            float aa[8] = {a0.x, a0.y, a0.z, a0.w, a1.x, a1.y, a1.z, a1.w};
            #pragma unroll
            for (int i = 0; i < 8; i++) {
                ull ap = pack2(aa[i]);
                #pragma unroll
                for (int j = 0; j < 4; j++)
                    ffma2(acc2[i][j], ap, bb[j]);
            }
        }

        if (has_next) {
            int nb = buf ^ 1;
            As[nb][akc + 0][arow] = av0.x;
            As[nb][akc + 1][arow] = av0.y;
            As[nb][akc + 2][arow] = av0.z;
            As[nb][akc + 3][arow] = av0.w;
            As[nb][akc + 8][arow] = av1.x;
            As[nb][akc + 9][arow] = av1.y;
            As[nb][akc +10][arow] = av1.z;
            As[nb][akc +11][arow] = av1.w;
            *(float4*)&Bs[nb][brow][bc4]     = bv0;
            *(float4*)&Bs[nb][brow + 8][bc4] = bv1;
            __syncthreads();
            buf = nb;
        }
    }
    #undef XFORM_A
    #undef LOAD_B

    #pragma unroll
    for (int i = 0; i < 8; i++) {
        int row = bm + row0 + (i & 3) + (i >> 2) * 16;
        float* crow = C + (size_t)row * Nc;
        int c0 = bn + col0;
        int c1 = bn + col0 + 32;
        float2 p0 = *reinterpret_cast<float2*>(&acc2[i][0]);
        float2 p1 = *reinterpret_cast<float2*>(&acc2[i][1]);
        float2 p2 = *reinterpret_cast<float2*>(&acc2[i][2]);
        float2 p3 = *reinterpret_cast<float2*>(&acc2[i][3]);
        if (c1 + 3 < Nc) {
            float4 v0, v1;
            v0.x = p0.x + bias[c0 + 0];
            v0.y = p0.y + bias[c0 + 1];
            v0.z = p1.x + bias[c0 + 2];
            v0.w = p1.y + bias[c0 + 3];
            v1.x = p2.x + bias[c1 + 0];
            v1.y = p2.y + bias[c1 + 1];
            v1.z = p3.x + bias[c1 + 2];
            v1.w = p3.y + bias[c1 + 3];
            *(float4*)&crow[c0] = v0;
            *(float4*)&crow[c1] = v1;
        } else {
            float acc[8] = {p0.x, p0.y, p1.x, p1.y, p2.x, p2.y, p3.x, p3.y};
            #pragma unroll
            for (int j = 0; j < 8; j++) {
                int col = (j < 4) ? (c0 + j) : (c1 + j - 4);
                if (col < Nc) crow[col] = acc[j] + bias[col];
            }
        }
    }
}

// ---------------- generic fp32 tiled GEMM (kept for GEMM3 scatter path) ----------------
__global__ void gemm_kernel(const float* __restrict__ A, const float* __restrict__ B,
                            const float* __restrict__ bias,
                            const int* __restrict__ scatter,
                            float* __restrict__ C,
                            int M, int Nc, int K) {
    __shared__ float As[16][64];
    __shared__ float Bs[16][64];
    int tid = threadIdx.x;                // 256 threads
    int tx = tid & 15, ty = tid >> 4;
    int bm = blockIdx.y * 64, bn = blockIdx.x * 64;

    float acc[4][4] = {};
    int arow  = bm + (tid >> 2);
    int acol0 = (tid & 3) * 4;
    int brow0 = tid >> 4;
    int bcoll = (tid & 15) * 4;
    int bcol  = bn + bcoll;

    for (int k0 = 0; k0 < K; k0 += 16) {
        float4 av = make_float4(0.f, 0.f, 0.f, 0.f);
        if (arow < M) av = *(const float4*)&A[(size_t)arow * K + k0 + acol0];
        As[acol0 + 0][tid >> 2] = av.x;
        As[acol0 + 1][tid >> 2] = av.y;
        As[acol0 + 2][tid >> 2] = av.z;
        As[acol0 + 3][tid >> 2] = av.w;

        const float* Brow = &B[(size_t)(k0 + brow0) * Nc];
        float4 bv;
        if (bcol + 3 < Nc) bv = *(const float4*)&Brow[bcol];
        else {
            bv.x = (bcol + 0 < Nc) ? Brow[bcol + 0] : 0.f;
            bv.y = (bcol + 1 < Nc) ? Brow[bcol + 1] : 0.f;
            bv.z = (bcol + 2 < Nc) ? Brow[bcol + 2] : 0.f;
            bv.w = (bcol + 3 < Nc) ? Brow[bcol + 3] : 0.f;
        }
        *(float4*)&Bs[brow0][bcoll] = bv;
        __syncthreads();

        #pragma unroll
        for (int kk = 0; kk < 16; kk++) {
            float4 a4 = *(float4*)&As[kk][ty * 4];
            float4 b4 = *(float4*)&Bs[kk][tx * 4];
            float aa[4] = {a4.x, a4.y, a4.z, a4.w};
            float bb[4] = {b4.x, b4.y, b4.z, b4.w};
            #pragma unroll
            for (int i = 0; i < 4; i++)
                #pragma unroll
                for (int j = 0; j < 4; j++)
                    acc[i][j] = fmaf(aa[i], bb[j], acc[i][j]);
        }
        __syncthreads();
    }

    #pragma unroll
    for (int i = 0; i < 4; i++) {
        int row = bm + ty * 4 + i;
        if (row >= M) break;
        float* crow;
        if (scatter) {
            int b = row / KC, t = row - b * KC;
            int grow = b * LL + scatter[b * KC + t];
            crow = C + (size_t)grow * Nc;
        } else {
            crow = C + (size_t)row * Nc;
        }
        #pragma unroll
        for (int j = 0; j < 4; j++) {
            int col = bn + tx * 4 + j;
            if (col < Nc) {
                float v = acc[i][j] + bias[col];
                if (scatter) crow[col] += v;
                else         crow[col]  = v;
            }
        }
    }
}

// ---------------- K5: per-token sparse head attention (top-1), float4 loads ----------------
__global__ void attn_kernel() {
    __shared__ float sq[2][QKVW];
    __shared__ float ssc[2][36];
    __shared__ int   sg[2][8];
    int w = threadIdx.x >> 5, lane = threadIdx.x & 31;
    int n = blockIdx.x * 2 + w;

    const float4* row4 = (const float4*)(g_qkv + (size_t)n * QKVW);  // 252 float4
    float4* sq4 = (float4*)sq[w];
    for (int i = lane; i < QKVW / 4; i += 32) sq4[i] = row4[i];
    __syncwarp();

    for (int p = lane; p < 36; p += 32) {
        int h = p / 6, g = p - h * 6;
        const float* qp = &sq[w][h * HDC];
        const float* kp = &sq[w][EC + g * HDC];
        float s = 0.f;
        #pragma unroll
        for (int d = 0; d < HDC; d++) s = fmaf(qp[d], kp[d], s);
        ssc[w][p] = s;
    }
    __syncwarp();

    if (lane < HEADSC) {
        float bv = ssc[w][lane * 6]; int bg = 0;
        #pragma unroll
        for (int g = 1; g < 6; g++) {
            float s = ssc[w][lane * 6 + g];
            if (s > bv) { bv = s; bg = g; }
        }
        sg[w][lane] = bg;
    }
    __syncwarp();

    float ss = 0.f;
    for (int e = lane; e < EC; e += 32) {
        int h = e % 6, d = e / 6;            // e = d*HEADS + h
        float v = sq[w][2 * EC + sg[w][h] * HDC + d];
        g_att[(size_t)n * EC + e] = v;
        ss = fmaf(v, v, ss);
    }
    #pragma unroll
    for (int o = 16; o; o >>= 1) ss += __shfl_xor_sync(0xffffffffu, ss, o);
    if (lane == 0) g_imp[n] = ss;
}

// ---------------- K6: exact top-KC via in-smem bitonic sort (JAX tie semantics) ----------------
__global__ void topk_kernel() {
    __shared__ unsigned long long skey[LL];
    int b = blockIdx.x;
    int tid = threadIdx.x;  // 256
    for (int j = tid; j < LL; j += 256) {
        unsigned int bits = __float_as_uint(g_imp[b * LL + j]);
        skey[j] = (((unsigned long long)bits) << 12) | (unsigned long long)(LL - 1 - j);
    }
    __syncthreads();

    for (int k = 2; k <= LL; k <<= 1) {
        for (int j = k >> 1; j > 0; j >>= 1) {
            for (int p = tid; p < LL / 2; p += 256) {
                int i = ((p & ~(j - 1)) << 1) | (p & (j - 1));
                int partner = i | j;
                unsigned long long a = skey[i], c = skey[partner];
                bool desc = ((i & k) == 0);
                if (desc ? (a < c) : (a > c)) { skey[i] = c; skey[partner] = a; }
            }
            __syncthreads();
        }
    }

    for (int r = tid; r < KC; r += 256) {
        g_idx[b * KC + r] = (LL - 1) - (int)(skey[r] & 0xFFFULL);
    }
}

// ---------------- K7: gather + causal depthwise conv (DCONV=4, left pad 3) ----------------
__global__ void conv_kernel(const float* __restrict__ conv_w) {
    int bt = blockIdx.x;
    int b = bt / KC, t = bt - b * KC;
    int e = threadIdx.x;  // 336 threads
    float acc = 0.f;
    #pragma unroll
    for (int j = 0; j < 4; j++) {
        int tj = t - 3 + j;
        if (tj >= 0) {
            int r = g_idx[b * KC + tj];
            acc = fmaf(conv_w[e * 4 + j], g_att[((size_t)b * LL + r) * EC + e], acc);
        }
    }
    g_xct[((size_t)b * EC + e) * KC + t] = acc;
}

// ---------------- K8a: v[d] = A^d @ sigmoid(Bp), d = 0..DTAP-1 (1 warp) ----------------
__global__ void vpow_kernel(const float* __restrict__ A, const float* __restrict__ Bp) {
    int lane = threadIdx.x;       // 32 threads
    int i = lane & 15;
    float a[DST];
    #pragma unroll
    for (int j = 0; j < DST; j++) a[j] = A[i * DST + j];
    float v = 1.f / (1.f + expf(-Bp[i]));
    for (int d = 0; d < DTAP; d++) {
        if (lane < DST) g_v[d * DST + i] = v;
        float nv = 0.f;
        #pragma unroll
        for (int j = 0; j < DST; j++)
            nv = fmaf(a[j], __shfl_sync(0xffffffffu, v, j), nv);
        v = nv;
    }
}

// ---------------- K8b: w[e][d] = sigmoid(Cp[e]) . v[d] ----------------
__global__ void wcoef_kernel(const float* __restrict__ Cp) {
    __shared__ float sc[DST];
    int e = blockIdx.x;
    int d = threadIdx.x;          // DTAP threads
    if (d < DST) sc[d] = 1.f / (1.f + expf(-Cp[e * DST + d]));
    __syncthreads();
    float acc = 0.f;
    #pragma unroll
    for (int i = 0; i < DST; i++) acc = fmaf(sc[i], g_v[d * DST + i], acc);
    g_w[e * DTAP + d] = acc;
}

// ---------------- K8c: causal FIR over t ----------------
__global__ void fir_kernel() {
    __shared__ float xr[KC];
    __shared__ float wr[DTAP];
    int be = blockIdx.x;
    int b = be / EC, e = be - b * EC;
    int tid = threadIdx.x;        // 256
    const float* src = g_xct + (size_t)be * KC;
    for (int t = tid; t < KC; t += 256) xr[t] = src[t];
    if (tid < DTAP) wr[tid] = g_w[e * DTAP + tid];
    __syncthreads();
    for (int t = tid; t < KC; t += 256) {
        float acc = 0.f;
        int dmax = min(DTAP - 1, t);
        for (int d = 0; d <= dmax; d++)
            acc = fmaf(wr[d], xr[t - d], acc);
        g_ys[((size_t)b * KC + t) * EC + e] = acc;
    }
}

// ---------------- launch ----------------
extern "C" void kernel_launch(void* const* d_in, const int* in_sizes, int n_in,
                              void* d_out, int out_size) {
    const float* x      = (const float*)d_in[0];
    const float* alpha  = (const float*)d_in[1];
    const float* dyt_w  = (const float*)d_in[2];
    const float* dyt_b  = (const float*)d_in[3];
    const float* W_in   = (const float*)d_in[4];
    const float* b_in   = (const float*)d_in[5];
    const float* W_qkv  = (const float*)d_in[6];
    const float* b_qkv  = (const float*)d_in[7];
    const float* conv_w = (const float*)d_in[8];
    const float* A      = (const float*)d_in[9];
    const float* Bp     = (const float*)d_in[10];
    const float* Cp     = (const float*)d_in[11];
    const float* W_out  = (const float*)d_in[12];
    const float* b_out  = (const float*)d_in[13];
    float* out = (float*)d_out;

    float* p_xp;  cudaGetSymbolAddress((void**)&p_xp,  g_xp);
    float* p_nrm; cudaGetSymbolAddress((void**)&p_nrm, g_nrm);
    float* p_qkv; cudaGetSymbolAddress((void**)&p_qkv, g_qkv);
    float* p_ys;  cudaGetSymbolAddress((void**)&p_ys,  g_ys);
    int*   p_idx; cudaGetSymbolAddress((void**)&p_idx, g_idx);

    // SSM impulse-response taps (tiny, independent of the main chain)
    vpow_kernel<<<1, 32>>>(A, Bp);
    wcoef_kernel<<<EC, DTAP>>>(Cp);

    // residual base: out = x
    cudaMemcpyAsync(out, x, (size_t)NN * DIMC * sizeof(float),
                    cudaMemcpyDeviceToDevice, 0);

    // GEMM1 (DyT fused in A-loader): xp = (tanh(alpha*x)*w+b) @ W_in + b_in
    {
        dim3 grid((EC + 127) / 128, NN / 128);
        gemm128_kernel<<<grid, 256>>>(x, W_in, b_in, nullptr,
                                      dyt_w, dyt_b, alpha, p_xp, NN, EC, DIMC);
    }
    // row norms
    norm_kernel<<<NN / 8, 256>>>();
    // GEMM2: qkv = (xp / nrm) @ W_qkv + b_qkv
    {
        dim3 grid((QKVW + 127) / 128, NN / 128);
        gemm128_kernel<<<grid, 256>>>(p_xp, W_qkv, b_qkv, p_nrm,
                                      nullptr, nullptr, nullptr, p_qkv, NN, QKVW, EC);
    }
    // attention (top-1 per head) + importance
    attn_kernel<<<NN / 2, 64>>>();
    // exact top-KC per batch (bitonic sort)
    topk_kernel<<<BB, 256>>>();
    // gather + causal depthwise conv (transposed output)
    conv_kernel<<<BB * KC, EC>>>(conv_w);
    // SSM as causal FIR
    fir_kernel<<<BB * EC, 256>>>();
    // GEMM3 + scatter-add into residual
    {
        int M3 = BB * KC;
        dim3 grid((DIMC + 63) / 64, (M3 + 63) / 64);
        gemm_kernel<<<grid, 256>>>(p_ys, W_out, b_out, p_idx, out, M3, DIMC, EC);
    }
}

// round 16
// speedup vs baseline: 1.0617x; 1.0617x over previous
#include <cuda_runtime.h>
#include <cuda_bf16.h>
#include <math.h>

#define DIMC 512
#define EC   336
#define DST  16
#define HEADSC 6
#define HDC  56
#define BB   8
#define LL   4096
#define NN   32768        // B*L
#define KC   819          // int(L*0.2)
#define QKVW 1008         // 3*E
#define DTAP 128          // FIR truncation of the SSM impulse response

typedef unsigned long long ull;

// packed fp32x2 helpers (Blackwell FFMA2 — only reachable via PTX)
__device__ __forceinline__ ull pack2(float x) {
    ull r; asm("mov.b64 %0, {%1, %1};" : "=l"(r) : "f"(x)); return r;
}
__device__ __forceinline__ void ffma2(ull& d, ull a, ull b) {
    asm("fma.rn.f32x2 %0, %1, %2, %0;" : "+l"(d) : "l"(a), "l"(b));
}

// ---------------- scratch (device globals; no allocation) ----------------
__device__ __align__(128) float g_xp [(size_t)NN * EC];       // DyT(x) @ W_in + b_in
__device__ __align__(128) float g_nrm[NN];                    // max(||xp||, 1e-12)
__device__ __align__(128) float g_qkv[(size_t)NN * QKVW];     // qkv
__device__ __align__(128) float g_att[(size_t)NN * EC];       // attn out, e=d*6+h
__device__ __align__(128) float g_imp[NN];                    // sum-of-squares importance
__device__ __align__(128) int   g_idx[BB * KC];               // top-KC indices, rank order
__device__ __align__(128) float g_xct[(size_t)BB * EC * KC];  // conv output, (b,e,t)
__device__ __align__(128) float g_ys [(size_t)BB * KC * EC];  // FIR output (b,t,e)
__device__ __align__(128) float g_v  [DTAP * DST];            // A^d @ sigmoid(Bp)
__device__ __align__(128) float g_w  [EC * DTAP];             // FIR taps per channel

// ---------------- K3: row norms of xp ----------------
__global__ void norm_kernel() {
    int warp = (blockIdx.x * blockDim.x + threadIdx.x) >> 5;
    int lane = threadIdx.x & 31;
    if (warp >= NN) return;
    const float* row = g_xp + (size_t)warp * EC;
    float s = 0.f;
    for (int e = lane; e < EC; e += 32) { float v = row[e]; s = fmaf(v, v, s); }
    #pragma unroll
    for (int o = 16; o; o >>= 1) s += __shfl_xor_sync(0xffffffffu, s, o);
    if (lane == 0) g_nrm[warp] = fmaxf(sqrtf(s), 1e-12f);
}

// ---------------- fast fp32 GEMM: 128x128 tile, k-chunk 8, warp-tiled 8x8, FFMA2 ----------------
// (R13 configuration — k-chunk 16 regressed: register pressure at the regs=128 ceiling)
// C[M,Nc] = f(A)[M,K] @ B[K,Nc] + bias[n]
//   f = DyT (tanh(alpha*a)*dytw[k]+dytb[k]) when dytw != nullptr  (elementwise, bit-exact)
//   f = a / rowdiv[m]                       when rowdiv != nullptr
// Requires: M % 128 == 0, K % 8 == 0.
// Per-element accumulation: single register, strictly ascending k -> bit-identical.
__global__ void __launch_bounds__(256, 2)
gemm128_kernel(const float* __restrict__ A, const float* __restrict__ B,
               const float* __restrict__ bias,
               const float* __restrict__ rowdiv,
               const float* __restrict__ dytw,
               const float* __restrict__ dytb,
               const float* __restrict__ alphap,
               float* __restrict__ C,
               int M, int Nc, int K) {
    __shared__ float As[2][8][128];
    __shared__ float Bs[2][8][128];
    int tid = threadIdx.x;                 // 256 threads
    int bm = blockIdx.y * 128, bn = blockIdx.x * 128;

    int wid = tid >> 5, lane = tid & 31;
    int wm = wid & 3, wn = wid >> 2;       // 4 x 2 warps
    int lm = lane >> 3, ln = lane & 7;     // 4 x 8 lanes
    int row0 = wm * 32 + lm * 4;
    int col0 = wn * 64 + ln * 4;

    int arow = tid >> 1;                   // 0..127
    int akc  = (tid & 1) * 4;              // 0 or 4
    const float* Aptr = A + (size_t)(bm + arow) * K + akc;
    float dv = rowdiv ? rowdiv[bm + arow] : 1.f;
    float alp = alphap ? alphap[0] : 0.f;

    int brow = tid >> 5;                   // 0..7
    int bc4  = (tid & 31) * 4;             // 0..124
    int bcol = bn + bc4;

    ull acc2[8][4] = {};

    // A element transform (applied in the loader, elementwise -> bit-exact)
    #define LOAD_A(av, koff)                                               \
        {                                                                  \
            av = *(const float4*)(Aptr + (koff));                          \
            if (dytw) {                                                    \
                float4 w4 = *(const float4*)&dytw[(koff) + akc];           \
                float4 b4 = *(const float4*)&dytb[(koff) + akc];           \
                av.x = tanhf(alp * av.x) * w4.x + b4.x;                    \
                av.y = tanhf(alp * av.y) * w4.y + b4.y;                    \
                av.z = tanhf(alp * av.z) * w4.z + b4.z;                    \
                av.w = tanhf(alp * av.w) * w4.w + b4.w;                    \
            } else if (rowdiv) {                                           \
                av.x /= dv; av.y /= dv; av.z /= dv; av.w /= dv;            \
            }                                                              \
        }

    {
        float4 av;
        LOAD_A(av, 0);
        As[0][akc + 0][arow] = av.x;
        As[0][akc + 1][arow] = av.y;
        As[0][akc + 2][arow] = av.z;
        As[0][akc + 3][arow] = av.w;
        const float* Brow = B + (size_t)brow * Nc;
        float4 bv;
        if (bcol + 3 < Nc) bv = *(const float4*)&Brow[bcol];
        else {
            bv.x = (bcol + 0 < Nc) ? Brow[bcol + 0] : 0.f;
            bv.y = (bcol + 1 < Nc) ? Brow[bcol + 1] : 0.f;
            bv.z = (bcol + 2 < Nc) ? Brow[bcol + 2] : 0.f;
            bv.w = (bcol + 3 < Nc) ? Brow[bcol + 3] : 0.f;
        }
        *(float4*)&Bs[0][brow][bc4] = bv;
    }
    __syncthreads();

    int buf = 0;
    for (int k0 = 0; k0 < K; k0 += 8) {
        bool has_next = (k0 + 8) < K;
        float4 av, bv;
        if (has_next) {
            LOAD_A(av, k0 + 8);
            const float* Brow = B + (size_t)(k0 + 8 + brow) * Nc;
            if (bcol + 3 < Nc) bv = *(const float4*)&Brow[bcol];
            else {
                bv.x = (bcol + 0 < Nc) ? Brow[bcol + 0] : 0.f;
                bv.y = (bcol + 1 < Nc) ? Brow[bcol + 1] : 0.f;
                bv.z = (bcol + 2 < Nc) ? Brow[bcol + 2] : 0.f;
                bv.w = (bcol + 3 < Nc) ? Brow[bcol + 3] : 0.f;
            }
        }

        #pragma unroll
        for (int kk = 0; kk < 8; kk++) {
            float4 a0 = *(float4*)&As[buf][kk][row0];
            float4 a1 = *(float4*)&As[buf][kk][row0 + 16];
            ulonglong2 bq0 = *(ulonglong2*)&Bs[buf][kk][col0];
            ulonglong2 bq1 = *(ulonglong2*)&Bs[buf][kk][col0 + 32];
            ull bb[4] = {bq0.x, bq0.y, bq1.x, bq1.y};
            float aa[8] = {a0.x, a0.y, a0.z, a0.w, a1.x, a1.y, a1.z, a1.w};
            #pragma unroll
            for (int i = 0; i < 8; i++) {
                ull ap = pack2(aa[i]);
                #pragma unroll
                for (int j = 0; j < 4; j++)
                    ffma2(acc2[i][j], ap, bb[j]);
            }
        }

        if (has_next) {
            int nb = buf ^ 1;
            As[nb][akc + 0][arow] = av.x;
            As[nb][akc + 1][arow] = av.y;
            As[nb][akc + 2][arow] = av.z;
            As[nb][akc + 3][arow] = av.w;
            *(float4*)&Bs[nb][brow][bc4] = bv;
            __syncthreads();
            buf = nb;
        }
    }
    #undef LOAD_A

    #pragma unroll
    for (int i = 0; i < 8; i++) {
        int row = bm + row0 + (i & 3) + (i >> 2) * 16;
        float* crow = C + (size_t)row * Nc;
        int c0 = bn + col0;
        int c1 = bn + col0 + 32;
        float2 p0 = *reinterpret_cast<float2*>(&acc2[i][0]);
        float2 p1 = *reinterpret_cast<float2*>(&acc2[i][1]);
        float2 p2 = *reinterpret_cast<float2*>(&acc2[i][2]);
        float2 p3 = *reinterpret_cast<float2*>(&acc2[i][3]);
        if (c1 + 3 < Nc) {
            float4 v0, v1;
            v0.x = p0.x + bias[c0 + 0];
            v0.y = p0.y + bias[c0 + 1];
            v0.z = p1.x + bias[c0 + 2];
            v0.w = p1.y + bias[c0 + 3];
            v1.x = p2.x + bias[c1 + 0];
            v1.y = p2.y + bias[c1 + 1];
            v1.z = p3.x + bias[c1 + 2];
            v1.w = p3.y + bias[c1 + 3];
            *(float4*)&crow[c0] = v0;
            *(float4*)&crow[c1] = v1;
        } else {
            float acc[8] = {p0.x, p0.y, p1.x, p1.y, p2.x, p2.y, p3.x, p3.y};
            #pragma unroll
            for (int j = 0; j < 8; j++) {
                int col = (j < 4) ? (c0 + j) : (c1 + j - 4);
                if (col < Nc) crow[col] = acc[j] + bias[col];
            }
        }
    }
}

// ---------------- generic fp32 tiled GEMM (kept for GEMM3 scatter path) ----------------
__global__ void gemm_kernel(const float* __restrict__ A, const float* __restrict__ B,
                            const float* __restrict__ bias,
                            const int* __restrict__ scatter,
                            float* __restrict__ C,
                            int M, int Nc, int K) {
    __shared__ float As[16][64];
    __shared__ float Bs[16][64];
    int tid = threadIdx.x;                // 256 threads
    int tx = tid & 15, ty = tid >> 4;
    int bm = blockIdx.y * 64, bn = blockIdx.x * 64;

    float acc[4][4] = {};
    int arow  = bm + (tid >> 2);
    int acol0 = (tid & 3) * 4;
    int brow0 = tid >> 4;
    int bcoll = (tid & 15) * 4;
    int bcol  = bn + bcoll;

    for (int k0 = 0; k0 < K; k0 += 16) {
        float4 av = make_float4(0.f, 0.f, 0.f, 0.f);
        if (arow < M) av = *(const float4*)&A[(size_t)arow * K + k0 + acol0];
        As[acol0 + 0][tid >> 2] = av.x;
        As[acol0 + 1][tid >> 2] = av.y;
        As[acol0 + 2][tid >> 2] = av.z;
        As[acol0 + 3][tid >> 2] = av.w;

        const float* Brow = &B[(size_t)(k0 + brow0) * Nc];
        float4 bv;
        if (bcol + 3 < Nc) bv = *(const float4*)&Brow[bcol];
        else {
            bv.x = (bcol + 0 < Nc) ? Brow[bcol + 0] : 0.f;
            bv.y = (bcol + 1 < Nc) ? Brow[bcol + 1] : 0.f;
            bv.z = (bcol + 2 < Nc) ? Brow[bcol + 2] : 0.f;
            bv.w = (bcol + 3 < Nc) ? Brow[bcol + 3] : 0.f;
        }
        *(float4*)&Bs[brow0][bcoll] = bv;
        __syncthreads();

        #pragma unroll
        for (int kk = 0; kk < 16; kk++) {
            float4 a4 = *(float4*)&As[kk][ty * 4];
            float4 b4 = *(float4*)&Bs[kk][tx * 4];
            float aa[4] = {a4.x, a4.y, a4.z, a4.w};
            float bb[4] = {b4.x, b4.y, b4.z, b4.w};
            #pragma unroll
            for (int i = 0; i < 4; i++)
                #pragma unroll
                for (int j = 0; j < 4; j++)
                    acc[i][j] = fmaf(aa[i], bb[j], acc[i][j]);
        }
        __syncthreads();
    }

    #pragma unroll
    for (int i = 0; i < 4; i++) {
        int row = bm + ty * 4 + i;
        if (row >= M) break;
        float* crow;
        if (scatter) {
            int b = row / KC, t = row - b * KC;
            int grow = b * LL + scatter[b * KC + t];
            crow = C + (size_t)grow * Nc;
        } else {
            crow = C + (size_t)row * Nc;
        }
        #pragma unroll
        for (int j = 0; j < 4; j++) {
            int col = bn + tx * 4 + j;
            if (col < Nc) {
                float v = acc[i][j] + bias[col];
                if (scatter) crow[col] += v;
                else         crow[col]  = v;
            }
        }
    }
}

// ---------------- K5: per-token sparse head attention (top-1), float4 loads ----------------
__global__ void attn_kernel() {
    __shared__ float sq[2][QKVW];
    __shared__ float ssc[2][36];
    __shared__ int   sg[2][8];
    int w = threadIdx.x >> 5, lane = threadIdx.x & 31;
    int n = blockIdx.x * 2 + w;

    const float4* row4 = (const float4*)(g_qkv + (size_t)n * QKVW);  // 252 float4
    float4* sq4 = (float4*)sq[w];
    for (int i = lane; i < QKVW / 4; i += 32) sq4[i] = row4[i];
    __syncwarp();

    for (int p = lane; p < 36; p += 32) {
        int h = p / 6, g = p - h * 6;
        const float* qp = &sq[w][h * HDC];
        const float* kp = &sq[w][EC + g * HDC];
        float s = 0.f;
        #pragma unroll
        for (int d = 0; d < HDC; d++) s = fmaf(qp[d], kp[d], s);
        ssc[w][p] = s;
    }
    __syncwarp();

    if (lane < HEADSC) {
        float bv = ssc[w][lane * 6]; int bg = 0;
        #pragma unroll
        for (int g = 1; g < 6; g++) {
            float s = ssc[w][lane * 6 + g];
            if (s > bv) { bv = s; bg = g; }
        }
        sg[w][lane] = bg;
    }
    __syncwarp();

    float ss = 0.f;
    for (int e = lane; e < EC; e += 32) {
        int h = e % 6, d = e / 6;            // e = d*HEADS + h
        float v = sq[w][2 * EC + sg[w][h] * HDC + d];
        g_att[(size_t)n * EC + e] = v;
        ss = fmaf(v, v, ss);
    }
    #pragma unroll
    for (int o = 16; o; o >>= 1) ss += __shfl_xor_sync(0xffffffffu, ss, o);
    if (lane == 0) g_imp[n] = ss;
}

// ---------------- K6: exact top-KC via in-smem bitonic sort (JAX tie semantics) ----------------
__global__ void topk_kernel() {
    __shared__ unsigned long long skey[LL];
    int b = blockIdx.x;
    int tid = threadIdx.x;  // 256
    for (int j = tid; j < LL; j += 256) {
        unsigned int bits = __float_as_uint(g_imp[b * LL + j]);
        skey[j] = (((unsigned long long)bits) << 12) | (unsigned long long)(LL - 1 - j);
    }
    __syncthreads();

    for (int k = 2; k <= LL; k <<= 1) {
        for (int j = k >> 1; j > 0; j >>= 1) {
            for (int p = tid; p < LL / 2; p += 256) {
                int i = ((p & ~(j - 1)) << 1) | (p & (j - 1));
                int partner = i | j;
                unsigned long long a = skey[i], c = skey[partner];
                bool desc = ((i & k) == 0);
                if (desc ? (a < c) : (a > c)) { skey[i] = c; skey[partner] = a; }
            }
            __syncthreads();
        }
    }

    for (int r = tid; r < KC; r += 256) {
        g_idx[b * KC + r] = (LL - 1) - (int)(skey[r] & 0xFFFULL);
    }
}

// ---------------- K7: gather + causal depthwise conv (DCONV=4, left pad 3) ----------------
__global__ void conv_kernel(const float* __restrict__ conv_w) {
    int bt = blockIdx.x;
    int b = bt / KC, t = bt - b * KC;
    int e = threadIdx.x;  // 336 threads
    float acc = 0.f;
    #pragma unroll
    for (int j = 0; j < 4; j++) {
        int tj = t - 3 + j;
        if (tj >= 0) {
            int r = g_idx[b * KC + tj];
            acc = fmaf(conv_w[e * 4 + j], g_att[((size_t)b * LL + r) * EC + e], acc);
        }
    }
    g_xct[((size_t)b * EC + e) * KC + t] = acc;
}

// ---------------- K8a: v[d] = A^d @ sigmoid(Bp), d = 0..DTAP-1 (1 warp) ----------------
__global__ void vpow_kernel(const float* __restrict__ A, const float* __restrict__ Bp) {
    int lane = threadIdx.x;       // 32 threads
    int i = lane & 15;
    float a[DST];
    #pragma unroll
    for (int j = 0; j < DST; j++) a[j] = A[i * DST + j];
    float v = 1.f / (1.f + expf(-Bp[i]));
    for (int d = 0; d < DTAP; d++) {
        if (lane < DST) g_v[d * DST + i] = v;
        float nv = 0.f;
        #pragma unroll
        for (int j = 0; j < DST; j++)
            nv = fmaf(a[j], __shfl_sync(0xffffffffu, v, j), nv);
        v = nv;
    }
}

// ---------------- K8b: w[e][d] = sigmoid(Cp[e]) . v[d] ----------------
__global__ void wcoef_kernel(const float* __restrict__ Cp) {
    __shared__ float sc[DST];
    int e = blockIdx.x;
    int d = threadIdx.x;          // DTAP threads
    if (d < DST) sc[d] = 1.f / (1.f + expf(-Cp[e * DST + d]));
    __syncthreads();
    float acc = 0.f;
    #pragma unroll
    for (int i = 0; i < DST; i++) acc = fmaf(sc[i], g_v[d * DST + i], acc);
    g_w[e * DTAP + d] = acc;
}

// ---------------- K8c: causal FIR over t ----------------
__global__ void fir_kernel() {
    __shared__ float xr[KC];
    __shared__ float wr[DTAP];
    int be = blockIdx.x;
    int b = be / EC, e = be - b * EC;
    int tid = threadIdx.x;        // 256
    const float* src = g_xct + (size_t)be * KC;
    for (int t = tid; t < KC; t += 256) xr[t] = src[t];
    if (tid < DTAP) wr[tid] = g_w[e * DTAP + tid];
    __syncthreads();
    for (int t = tid; t < KC; t += 256) {
        float acc = 0.f;
        int dmax = min(DTAP - 1, t);
        for (int d = 0; d <= dmax; d++)
            acc = fmaf(wr[d], xr[t - d], acc);
        g_ys[((size_t)b * KC + t) * EC + e] = acc;
    }
}

// ---------------- launch ----------------
extern "C" void kernel_launch(void* const* d_in, const int* in_sizes, int n_in,
                              void* d_out, int out_size) {
    const float* x      = (const float*)d_in[0];
    const float* alpha  = (const float*)d_in[1];
    const float* dyt_w  = (const float*)d_in[2];
    const float* dyt_b  = (const float*)d_in[3];
    const float* W_in   = (const float*)d_in[4];
    const float* b_in   = (const float*)d_in[5];
    const float* W_qkv  = (const float*)d_in[6];
    const float* b_qkv  = (const float*)d_in[7];
    const float* conv_w = (const float*)d_in[8];
    const float* A      = (const float*)d_in[9];
    const float* Bp     = (const float*)d_in[10];
    const float* Cp     = (const float*)d_in[11];
    const float* W_out  = (const float*)d_in[12];
    const float* b_out  = (const float*)d_in[13];
    float* out = (float*)d_out;

    float* p_xp;  cudaGetSymbolAddress((void**)&p_xp,  g_xp);
    float* p_nrm; cudaGetSymbolAddress((void**)&p_nrm, g_nrm);
    float* p_qkv; cudaGetSymbolAddress((void**)&p_qkv, g_qkv);
    float* p_ys;  cudaGetSymbolAddress((void**)&p_ys,  g_ys);
    int*   p_idx; cudaGetSymbolAddress((void**)&p_idx, g_idx);

    // SSM impulse-response taps (tiny, independent of the main chain)
    vpow_kernel<<<1, 32>>>(A, Bp);
    wcoef_kernel<<<EC, DTAP>>>(Cp);

    // residual base: out = x
    cudaMemcpyAsync(out, x, (size_t)NN * DIMC * sizeof(float),
                    cudaMemcpyDeviceToDevice, 0);

    // GEMM1 (DyT fused in A-loader): xp = (tanh(alpha*x)*w+b) @ W_in + b_in
    {
        dim3 grid((EC + 127) / 128, NN / 128);
        gemm128_kernel<<<grid, 256>>>(x, W_in, b_in, nullptr,
                                      dyt_w, dyt_b, alpha, p_xp, NN, EC, DIMC);
    }
    // row norms
    norm_kernel<<<NN / 8, 256>>>();
    // GEMM2: qkv = (xp / nrm) @ W_qkv + b_qkv
    {
        dim3 grid((QKVW + 127) / 128, NN / 128);
        gemm128_kernel<<<grid, 256>>>(p_xp, W_qkv, b_qkv, p_nrm,
                                      nullptr, nullptr, nullptr, p_qkv, NN, QKVW, EC);
    }
    // attention (top-1 per head) + importance
    attn_kernel<<<NN / 2, 64>>>();
    // exact top-KC per batch (bitonic sort)
    topk_kernel<<<BB, 256>>>();
    // gather + causal depthwise conv (transposed output)
    conv_kernel<<<BB * KC, EC>>>(conv_w);
    // SSM as causal FIR
    fir_kernel<<<BB * EC, 256>>>();
    // GEMM3 + scatter-add into residual
    {
        int M3 = BB * KC;
        dim3 grid((DIMC + 63) / 64, (M3 + 63) / 64);
        gemm_kernel<<<grid, 256>>>(p_ys, W_out, b_out, p_idx, out, M3, DIMC, EC);
    }
}